// round 7
// baseline (speedup 1.0000x reference)
#include <cuda_runtime.h>
#include <cuda_bf16.h>

#define IN_F  8192
#define OUT_F 8192
#define THRESH 50.0f

// ======================= Kernel 1: pure-read masked GEMV ====================
// warp-per-row, butterfly reduce, zero barriers, zero smem.
#define G_THREADS 256
#define G_WARPS   (G_THREADS / 32)
#define G_V4      (IN_F / 4 / 32)     // 64 float4 per lane
#define G_UNROLL  8

__global__ __launch_bounds__(G_THREADS)
void snn_gemv_kernel(const float* __restrict__ x,
                     const float* __restrict__ syn,
                     const float* __restrict__ mem,
                     const float* __restrict__ thr,
                     const float* __restrict__ refr,
                     float* __restrict__ out_spk,
                     float* __restrict__ out_mem,
                     float* __restrict__ out_refr)
{
    const int warp = threadIdx.x >> 5;
    const int lane = threadIdx.x & 31;
    const int row  = blockIdx.x * G_WARPS + warp;

    const float4* __restrict__ x4 = reinterpret_cast<const float4*>(x);
    const float4* __restrict__ syn4 =
        reinterpret_cast<const float4*>(syn + (size_t)row * IN_F);

    float acc = 0.0f;
    #pragma unroll 2
    for (int c = 0; c < G_V4; c += G_UNROLL) {
        float4 s[G_UNROLL];
        #pragma unroll
        for (int j = 0; j < G_UNROLL; ++j)
            s[j] = __ldcs(&syn4[lane + (c + j) * 32]);
        #pragma unroll
        for (int j = 0; j < G_UNROLL; ++j) {
            const float4 xv = __ldca(&x4[lane + (c + j) * 32]);  // L1-resident
            acc += (s[j].x > THRESH) ? xv.x : 0.0f;
            acc += (s[j].y > THRESH) ? xv.y : 0.0f;
            acc += (s[j].z > THRESH) ? xv.z : 0.0f;
            acc += (s[j].w > THRESH) ? xv.w : 0.0f;
        }
    }
    #pragma unroll
    for (int o = 16; o > 0; o >>= 1)
        acc += __shfl_xor_sync(0xffffffffu, acc, o);

    if (lane == 0) {
        const float r     = __ldg(&refr[row]);
        const float v_mem = __ldg(&mem[row]) * 0.5f + acc * (1.0f - r * 0.5f);
        const float sp    = (v_mem >= __ldg(&thr[row])) ? 1.0f : 0.0f;
        out_spk[row]  = sp;
        out_mem[row]  = v_mem * (1.0f - sp);
        out_refr[row] = fminf(fmaxf(r + sp - 0.1f, 0.0f), 1.0f);
    }
}

// ================= Kernel 2: trace stream (read + write, no sync) ===========
// CTA-per-row, 8 float4 per thread, stores stream from iteration 0.
#define T_THREADS 256
#define T_V4      (IN_F / 4 / T_THREADS)   // 8 float4 per thread

__global__ __launch_bounds__(T_THREADS)
void snn_trace_kernel(const float* __restrict__ x,
                      const float* __restrict__ trace,
                      const float* __restrict__ spk,
                      float* __restrict__ out_trace)
{
    const int row = blockIdx.x;
    const int tid = threadIdx.x;
    const float sp = __ldg(&spk[row]);     // uniform per CTA, L2-hot

    const float4* __restrict__ x4 = reinterpret_cast<const float4*>(x);
    const float4* __restrict__ tr4 =
        reinterpret_cast<const float4*>(trace + (size_t)row * IN_F);
    float4* __restrict__ ot4 =
        reinterpret_cast<float4*>(out_trace + (size_t)row * IN_F);

    #pragma unroll
    for (int j = 0; j < T_V4; ++j) {
        const int idx = tid + j * T_THREADS;
        const float4 t  = __ldcs(&tr4[idx]);
        const float4 xv = __ldca(&x4[idx]);
        float4 o;
        o.x = fminf(fmaxf(fmaf(t.x, 0.8f, sp * xv.x), 0.0f), 5.0f);
        o.y = fminf(fmaxf(fmaf(t.y, 0.8f, sp * xv.y), 0.0f), 5.0f);
        o.z = fminf(fmaxf(fmaf(t.z, 0.8f, sp * xv.z), 0.0f), 5.0f);
        o.w = fminf(fmaxf(fmaf(t.w, 0.8f, sp * xv.w), 0.0f), 5.0f);
        __stcs(&ot4[idx], o);
    }
}

extern "C" void kernel_launch(void* const* d_in, const int* in_sizes, int n_in,
                              void* d_out, int out_size) {
    const float* x     = (const float*)d_in[0];  // spike_input        [8192]
    const float* syn   = (const float*)d_in[1];  // synapse_states     [8192*8192]
    const float* mem   = (const float*)d_in[2];  // membrane_potential [8192]
    const float* thr   = (const float*)d_in[3];  // adaptive_threshold [8192]
    const float* trace = (const float*)d_in[4];  // eligibility_trace  [8192*8192]
    const float* refr  = (const float*)d_in[5];  // refractory_period  [8192]

    float* out = (float*)d_out;
    // output layout: spikes | new_membrane | new_trace | new_refractory
    float* out_spk   = out;
    float* out_mem   = out + OUT_F;
    float* out_trace = out + 2 * OUT_F;
    float* out_refr  = out + 2 * OUT_F + (size_t)OUT_F * IN_F;

    snn_gemv_kernel<<<OUT_F / G_WARPS, G_THREADS>>>(
        x, syn, mem, thr, refr, out_spk, out_mem, out_refr);

    snn_trace_kernel<<<OUT_F, T_THREADS>>>(x, trace, out_spk, out_trace);
}

// round 8
// speedup vs baseline: 1.1198x; 1.1198x over previous
#include <cuda_runtime.h>
#include <cuda_bf16.h>

#define IN_F  8192
#define OUT_F 8192
#define THRESH 50.0f
#define NTHREADS 256
#define VPT (IN_F / 4 / NTHREADS)   // 8 float4 per thread

__global__ __launch_bounds__(NTHREADS, 3)   // 80-reg budget: wider load batch
void snn_fused_kernel(const float* __restrict__ x,
                      const float* __restrict__ syn,
                      const float* __restrict__ mem,
                      const float* __restrict__ thr,
                      const float* __restrict__ trace,
                      const float* __restrict__ refr,
                      float* __restrict__ out_spk,
                      float* __restrict__ out_mem,
                      float* __restrict__ out_trace,
                      float* __restrict__ out_refr)
{
    __shared__ float sx[IN_F];              // 32 KB staged spike input
    __shared__ float swarp[NTHREADS / 32];

    const int row = blockIdx.x;
    const int tid = threadIdx.x;

    // ---- stage x into shared (x source stays L2/L1-resident: 32 KB total) ----
    {
        const float4* __restrict__ x4  = reinterpret_cast<const float4*>(x);
        float4*                    sx4 = reinterpret_cast<float4*>(sx);
        #pragma unroll
        for (int j = 0; j < VPT; ++j)
            sx4[tid + j * NTHREADS] = x4[tid + j * NTHREADS];
    }
    __syncthreads();

    const float4* __restrict__ syn4 =
        reinterpret_cast<const float4*>(syn + (size_t)row * IN_F);
    const float4* __restrict__ tr4 =
        reinterpret_cast<const float4*>(trace + (size_t)row * IN_F);
    const float4* __restrict__ sx4 = reinterpret_cast<const float4*>(sx);

    // ---- front-batch ALL trace loads (consumed last -> longest slack) ----
    float4 t[VPT];
    #pragma unroll
    for (int j = 0; j < VPT; ++j)
        t[j] = __ldcs(&tr4[tid + j * NTHREADS]);

    // ---- syn loads in two batches of 4, consumption interleaved ----
    float acc0 = 0.0f, acc1 = 0.0f;
    #pragma unroll
    for (int h = 0; h < 2; ++h) {
        float4 s[4];
        #pragma unroll
        for (int j = 0; j < 4; ++j)
            s[j] = __ldcs(&syn4[tid + (h * 4 + j) * NTHREADS]);
        #pragma unroll
        for (int j = 0; j < 4; ++j) {
            const float4 xv = sx4[tid + (h * 4 + j) * NTHREADS];
            acc0 += (s[j].x > THRESH) ? xv.x : 0.0f;
            acc1 += (s[j].y > THRESH) ? xv.y : 0.0f;
            acc0 += (s[j].z > THRESH) ? xv.z : 0.0f;
            acc1 += (s[j].w > THRESH) ? xv.w : 0.0f;
        }
    }
    float acc = acc0 + acc1;

    // warp reduce
    #pragma unroll
    for (int o = 16; o > 0; o >>= 1)
        acc += __shfl_down_sync(0xffffffffu, acc, o);
    if ((tid & 31) == 0) swarp[tid >> 5] = acc;
    __syncthreads();                            // the ONLY post-load barrier

    // all threads redundantly compute the (uniform) LIF scalars
    float current = 0.0f;
    #pragma unroll
    for (int w = 0; w < NTHREADS / 32; ++w) current += swarp[w];
    const float r     = refr[row];
    const float v_mem = mem[row] * 0.5f + current * (1.0f - r * 0.5f);
    const float sp    = (v_mem >= thr[row]) ? 1.0f : 0.0f;
    if (tid == 0) {
        out_spk[row]  = sp;
        out_mem[row]  = v_mem * (1.0f - sp);
        out_refr[row] = fminf(fmaxf(r + sp - 0.1f, 0.0f), 1.0f);
    }

    // ---- store pass: trace already in registers, only the store waited ----
    float4* __restrict__ ot4 =
        reinterpret_cast<float4*>(out_trace + (size_t)row * IN_F);
    #pragma unroll
    for (int j = 0; j < VPT; ++j) {
        const int idx = tid + j * NTHREADS;
        const float4 xv = sx4[idx];
        float4 o;
        o.x = fminf(fmaxf(fmaf(t[j].x, 0.8f, sp * xv.x), 0.0f), 5.0f);
        o.y = fminf(fmaxf(fmaf(t[j].y, 0.8f, sp * xv.y), 0.0f), 5.0f);
        o.z = fminf(fmaxf(fmaf(t[j].z, 0.8f, sp * xv.z), 0.0f), 5.0f);
        o.w = fminf(fmaxf(fmaf(t[j].w, 0.8f, sp * xv.w), 0.0f), 5.0f);
        __stcs(&ot4[idx], o);                   // streaming store, evict-first
    }
}

extern "C" void kernel_launch(void* const* d_in, const int* in_sizes, int n_in,
                              void* d_out, int out_size) {
    const float* x     = (const float*)d_in[0];  // spike_input        [8192]
    const float* syn   = (const float*)d_in[1];  // synapse_states     [8192*8192]
    const float* mem   = (const float*)d_in[2];  // membrane_potential [8192]
    const float* thr   = (const float*)d_in[3];  // adaptive_threshold [8192]
    const float* trace = (const float*)d_in[4];  // eligibility_trace  [8192*8192]
    const float* refr  = (const float*)d_in[5];  // refractory_period  [8192]

    float* out = (float*)d_out;
    // output layout: spikes | new_membrane | new_trace | new_refractory
    float* out_spk   = out;
    float* out_mem   = out + OUT_F;
    float* out_trace = out + 2 * OUT_F;
    float* out_refr  = out + 2 * OUT_F + (size_t)OUT_F * IN_F;

    snn_fused_kernel<<<OUT_F, NTHREADS>>>(x, syn, mem, thr, trace, refr,
                                          out_spk, out_mem, out_trace, out_refr);
}